// round 11
// baseline (speedup 1.0000x reference)
// R11: 4-wide packed weights (1x LDG.128/col/tile), parallel finalize, 32t score.
#include <cuda_runtime.h>
#include <math.h>

#define DEVINL __device__ __forceinline__
typedef unsigned long long ull;

constexpr int NJ  = 33;
constexpr int NF  = 52;
constexpr int NH  = 128;
constexpr int NB  = 64;     // batch
constexpr int NT  = 256;    // time
constexpr int BT  = NB * NT;
constexpr int NNZ = 69;

// Packed-weight scratch: quad-rows of 512 floats: {W[4p..4p+3][o]} per col o.
constexpr int QR0 = NF / 4;   // 13 quad-rows for K=52
constexpr int QR1 = NH / 4;   // 32 quad-rows for K=128
constexpr int OFF_W0 = 0;
constexpr int OFF_S0 = OFF_W0 + QR0 * 4 * NH;     // 6656
constexpr int OFF_W1 = OFF_S0 + QR0 * 4 * NH;     // 13312
constexpr int OFF_W2 = OFF_W1 + QR1 * 4 * NH;     // 29696
__device__ __align__(16) float g_WP[OFF_W2 + QR1 * 4 * NH];   // 46080 floats

// ---------------------------------------------------------------------------
// Hardcoded sparsity of the normalized adjacency (BODY_EDGES + self loops).
// ---------------------------------------------------------------------------
__constant__ int c_ptr[NJ + 1] = {
    0, 5, 6, 9, 10, 11, 14, 15, 18, 21, 22, 23, 30, 37, 40, 43, 45, 47,
    48, 49, 50, 51, 52, 53, 57, 61, 62, 63, 64, 65, 66, 67, 68, 69};
__constant__ int c_col[NNZ] = {
    0, 2, 5, 11, 12,
    1,
    0, 2, 7,
    3,
    4,
    0, 5, 8,
    6,
    2, 7, 11,
    5, 8, 12,
    9,
    10,
    0, 7, 11, 12, 13, 23, 24,
    0, 8, 11, 12, 14, 23, 24,
    11, 13, 15,
    12, 14, 16,
    13, 15,
    14, 16,
    17, 18, 19, 20, 21, 22,
    11, 12, 23, 24,
    11, 12, 23, 24,
    25, 26, 27, 28, 29, 30, 31, 32};
__constant__ int c_row[NNZ] = {
    0, 0, 0, 0, 0,
    1,
    2, 2, 2,
    3,
    4,
    5, 5, 5,
    6,
    7, 7, 7,
    8, 8, 8,
    9,
    10,
    11, 11, 11, 11, 11, 11, 11,
    12, 12, 12, 12, 12, 12, 12,
    13, 13, 13,
    14, 14, 14,
    15, 15,
    16, 16,
    17, 18, 19, 20, 21, 22,
    23, 23, 23, 23,
    24, 24, 24, 24,
    25, 26, 27, 28, 29, 30, 31, 32};

// Scratch (static __device__: allocation-guard safe)
__device__ float g_xt[(size_t)BT * NH];   // per-frame joint-mean features
__device__ float g_score[BT];             // attention logits

// ---------------------------------------------------------------------------
// helpers
// ---------------------------------------------------------------------------
DEVINL float gelu_f(float x) {
    return 0.5f * x * (1.0f + erff(x * 0.70710678118654752440f));
}

DEVINL void unpack2(ull v, float& lo, float& hi) {
    asm("mov.b64 {%0, %1}, %2;" : "=f"(lo), "=f"(hi) : "l"(v));
}
DEVINL void fma2(ull& d, ull a, ull b) {
    asm("fma.rn.f32x2 %0, %1, %2, %0;" : "+l"(d) : "l"(a), "l"(b));
}

// ---------------------------------------------------------------------------
// Weight pre-pack: WP[q][o] = {W[4q][o], W[4q+1][o], W[4q+2][o], W[4q+3][o]}.
// Flat float offset = q*512 + 4*o  =  (k=4q)*NH + 4*o.
// grid (32, 4), block 128.
// ---------------------------------------------------------------------------
__global__ void pack_weights_kernel(const float* __restrict__ W0,
                                    const float* __restrict__ S0,
                                    const float* __restrict__ W1,
                                    const float* __restrict__ W2) {
    int q = blockIdx.x;
    int m = blockIdx.y;
    int o = threadIdx.x;
    const float* src;
    float* dst;
    int nqr;
    if (m == 0)      { src = W0; dst = g_WP + OFF_W0; nqr = QR0; }
    else if (m == 1) { src = S0; dst = g_WP + OFF_S0; nqr = QR0; }
    else if (m == 2) { src = W1; dst = g_WP + OFF_W1; nqr = QR1; }
    else             { src = W2; dst = g_WP + OFF_W2; nqr = QR1; }
    if (q >= nqr) return;
    float4 v;
    v.x = src[(4 * q)     * NH + o];
    v.y = src[(4 * q + 1) * NH + o];
    v.z = src[(4 * q + 2) * NH + o];
    v.w = src[(4 * q + 3) * NH + o];
    reinterpret_cast<float4*>(dst)[q * NH + o] = v;
}

// Two-column GEMM chunk on quad-packed weights:
//   zA[j] = s_in[J0+j, :K] @ W[:, o]     zB[j] = ... @ W[:, o+64]
// Per k-tile, per column: ONE coalesced LDG.128 of 4 weight values.
template <int K, int LD, int J0, int JN>
DEVINL void gemm_chunk2(const float* __restrict__ WP, const float* s_in, int o,
                        float* zA, float* zB) {
    ull zA2[JN], zB2[JN];
#pragma unroll
    for (int j = 0; j < JN; j++) { zA2[j] = 0ull; zB2[j] = 0ull; }
#pragma unroll 2
    for (int k0 = 0; k0 < K; k0 += 4) {
        const ulonglong2* wq =
            reinterpret_cast<const ulonglong2*>(WP + k0 * NH);
        ulonglong2 wa = wq[o];        // {W[k0..k0+1][o], W[k0+2..k0+3][o]}
        ulonglong2 wb = wq[o + 64];   // col o+64
#pragma unroll
        for (int j = 0; j < JN; j++) {
            ulonglong2 a2 =
                *reinterpret_cast<const ulonglong2*>(s_in + (J0 + j) * LD + k0);
            fma2(zA2[j], a2.x, wa.x);
            fma2(zA2[j], a2.y, wa.y);
            fma2(zB2[j], a2.x, wb.x);
            fma2(zB2[j], a2.y, wb.y);
        }
    }
#pragma unroll
    for (int j = 0; j < JN; j++) {
        float lo, hi;
        unpack2(zA2[j], lo, hi);
        zA[j] = lo + hi;
        unpack2(zB2[j], lo, hi);
        zB[j] = lo + hi;
    }
}

// a = adj_norm @ h for one column, written to s_a[:, col].
DEVINL void adjmix_store(const float h[NJ], const float* s_v, float* s_a, int col) {
    float* p = s_a + col;
#define V(e) s_v[e]
    p[0 * NH]  = V(0)*h[0] + V(1)*h[2] + V(2)*h[5] + V(3)*h[11] + V(4)*h[12];
    p[1 * NH]  = V(5)*h[1];
    p[2 * NH]  = V(6)*h[0] + V(7)*h[2] + V(8)*h[7];
    p[3 * NH]  = V(9)*h[3];
    p[4 * NH]  = V(10)*h[4];
    p[5 * NH]  = V(11)*h[0] + V(12)*h[5] + V(13)*h[8];
    p[6 * NH]  = V(14)*h[6];
    p[7 * NH]  = V(15)*h[2] + V(16)*h[7] + V(17)*h[11];
    p[8 * NH]  = V(18)*h[5] + V(19)*h[8] + V(20)*h[12];
    p[9 * NH]  = V(21)*h[9];
    p[10 * NH] = V(22)*h[10];
    p[11 * NH] = V(23)*h[0] + V(24)*h[7] + V(25)*h[11] + V(26)*h[12] +
                 V(27)*h[13] + V(28)*h[23] + V(29)*h[24];
    p[12 * NH] = V(30)*h[0] + V(31)*h[8] + V(32)*h[11] + V(33)*h[12] +
                 V(34)*h[14] + V(35)*h[23] + V(36)*h[24];
    p[13 * NH] = V(37)*h[11] + V(38)*h[13] + V(39)*h[15];
    p[14 * NH] = V(40)*h[12] + V(41)*h[14] + V(42)*h[16];
    p[15 * NH] = V(43)*h[13] + V(44)*h[15];
    p[16 * NH] = V(45)*h[14] + V(46)*h[16];
    p[17 * NH] = V(47)*h[17];
    p[18 * NH] = V(48)*h[18];
    p[19 * NH] = V(49)*h[19];
    p[20 * NH] = V(50)*h[20];
    p[21 * NH] = V(51)*h[21];
    p[22 * NH] = V(52)*h[22];
    p[23 * NH] = V(53)*h[11] + V(54)*h[12] + V(55)*h[23] + V(56)*h[24];
    p[24 * NH] = V(57)*h[11] + V(58)*h[12] + V(59)*h[23] + V(60)*h[24];
    p[25 * NH] = V(61)*h[25];
    p[26 * NH] = V(62)*h[26];
    p[27 * NH] = V(63)*h[27];
    p[28 * NH] = V(64)*h[28];
    p[29 * NH] = V(65)*h[29];
    p[30 * NH] = V(66)*h[30];
    p[31 * NH] = V(67)*h[31];
    p[32 * NH] = V(68)*h[32];
#undef V
}

// ---------------------------------------------------------------------------
// Kernel 1: fused 3-layer GCN per frame.
// grid = BT, block = 64: thread handles output columns o and o+64.
// ---------------------------------------------------------------------------
__global__ void __launch_bounds__(64, 7) gcn_kernel(
    const float* __restrict__ x,   const float* __restrict__ adj,
    const float* __restrict__ b0,
    const float* __restrict__ sb0,
    const float* __restrict__ g0,  const float* __restrict__ be0,
    const float* __restrict__ m0,  const float* __restrict__ v0,
    const float* __restrict__ b1,
    const float* __restrict__ g1,  const float* __restrict__ be1,
    const float* __restrict__ m1,  const float* __restrict__ v1,
    const float* __restrict__ b2,
    const float* __restrict__ g2,  const float* __restrict__ be2,
    const float* __restrict__ m2,  const float* __restrict__ v2) {
    __shared__ __align__(16) float s_a[NJ * NH];   // 4224 floats
    __shared__ float s_v[NNZ + 3];

    // layer-0 staging overlaid inside s_a (dead after layer 0):
    float* s_x  = s_a;          // 1716 floats  [0, 1716)
    float* s_ax = s_a + 1728;   // 1716 floats  [1728, 3444)  (16B aligned)

    const int o  = threadIdx.x;        // 0..63
    const int ob = o + 64;
    const int bt = blockIdx.x;

    const float* WP0 = g_WP + OFF_W0;
    const float* SP0 = g_WP + OFF_S0;
    const float* WP1 = g_WP + OFF_W1;
    const float* WP2 = g_WP + OFF_W2;

    for (int e = o; e < NNZ; e += 64)
        s_v[e] = adj[c_row[e] * NJ + c_col[e]];

    // load x frame (1716 floats = 429 float4)
    const float4* xin = reinterpret_cast<const float4*>(x + (size_t)bt * (NJ * NF));
    float4* sx4 = reinterpret_cast<float4*>(s_x);
    for (int i = o; i < (NJ * NF) / 4; i += 64) sx4[i] = xin[i];
    __syncthreads();

    // layer-0 adjacency mix on the 52-dim input (sparse)
    for (int idx = o; idx < NJ * NF; idx += 64) {
        int n = idx / NF;
        int k = idx - n * NF;
        float acc = 0.f;
        int e1 = c_ptr[n + 1];
        for (int e = c_ptr[n]; e < e1; ++e)
            acc += s_v[e] * s_x[c_col[e] * NF + k];
        s_ax[idx] = acc;
    }
    __syncthreads();

    float hA[NJ], hB[NJ];
    float zA[11], zB[11];

    // ---- layer 0:  h = gelu(bn(ax @ W0)) + (x @ S0 + sb0) ----
    {
        float scA = g0[o]  * rsqrtf(v0[o]  + 1e-5f);
        float shA = (b0[o]  - m0[o])  * scA + be0[o];
        float scB = g0[ob] * rsqrtf(v0[ob] + 1e-5f);
        float shB = (b0[ob] - m0[ob]) * scB + be0[ob];

        gemm_chunk2<NF, NF, 0, 11>(WP0, s_ax, o, zA, zB);
#pragma unroll
        for (int j = 0; j < 11; j++) {
            hA[j] = gelu_f(zA[j] * scA + shA);
            hB[j] = gelu_f(zB[j] * scB + shB);
        }
        gemm_chunk2<NF, NF, 11, 11>(WP0, s_ax, o, zA, zB);
#pragma unroll
        for (int j = 0; j < 11; j++) {
            hA[11 + j] = gelu_f(zA[j] * scA + shA);
            hB[11 + j] = gelu_f(zB[j] * scB + shB);
        }
        gemm_chunk2<NF, NF, 22, 11>(WP0, s_ax, o, zA, zB);
#pragma unroll
        for (int j = 0; j < 11; j++) {
            hA[22 + j] = gelu_f(zA[j] * scA + shA);
            hB[22 + j] = gelu_f(zB[j] * scB + shB);
        }

        float sbA = sb0[o];
        float sbB = sb0[ob];
        gemm_chunk2<NF, NF, 0, 11>(SP0, s_x, o, zA, zB);
#pragma unroll
        for (int j = 0; j < 11; j++) { hA[j] += zA[j] + sbA; hB[j] += zB[j] + sbB; }
        gemm_chunk2<NF, NF, 11, 11>(SP0, s_x, o, zA, zB);
#pragma unroll
        for (int j = 0; j < 11; j++) { hA[11 + j] += zA[j] + sbA; hB[11 + j] += zB[j] + sbB; }
        gemm_chunk2<NF, NF, 22, 11>(SP0, s_x, o, zA, zB);
#pragma unroll
        for (int j = 0; j < 11; j++) { hA[22 + j] += zA[j] + sbA; hB[22 + j] += zB[j] + sbB; }
    }
    __syncthreads();   // layer-0 reads of s_x/s_ax done before s_a overwrite

    // ---- layer 1 (identity skip) ----
    adjmix_store(hA, s_v, s_a, o);
    adjmix_store(hB, s_v, s_a, ob);
    __syncthreads();
    {
        float scA = g1[o]  * rsqrtf(v1[o]  + 1e-5f);
        float shA = (b1[o]  - m1[o])  * scA + be1[o];
        float scB = g1[ob] * rsqrtf(v1[ob] + 1e-5f);
        float shB = (b1[ob] - m1[ob]) * scB + be1[ob];

        gemm_chunk2<NH, NH, 0, 11>(WP1, s_a, o, zA, zB);
#pragma unroll
        for (int j = 0; j < 11; j++) {
            hA[j] += gelu_f(zA[j] * scA + shA);
            hB[j] += gelu_f(zB[j] * scB + shB);
        }
        gemm_chunk2<NH, NH, 11, 11>(WP1, s_a, o, zA, zB);
#pragma unroll
        for (int j = 0; j < 11; j++) {
            hA[11 + j] += gelu_f(zA[j] * scA + shA);
            hB[11 + j] += gelu_f(zB[j] * scB + shB);
        }
        gemm_chunk2<NH, NH, 22, 11>(WP1, s_a, o, zA, zB);
#pragma unroll
        for (int j = 0; j < 11; j++) {
            hA[22 + j] += gelu_f(zA[j] * scA + shA);
            hB[22 + j] += gelu_f(zB[j] * scB + shB);
        }
    }
    __syncthreads();   // all reads of s_a done before overwrite

    // ---- layer 2 ----
    adjmix_store(hA, s_v, s_a, o);
    adjmix_store(hB, s_v, s_a, ob);
    __syncthreads();
    {
        float scA = g2[o]  * rsqrtf(v2[o]  + 1e-5f);
        float shA = (b2[o]  - m2[o])  * scA + be2[o];
        float scB = g2[ob] * rsqrtf(v2[ob] + 1e-5f);
        float shB = (b2[ob] - m2[ob]) * scB + be2[ob];

        gemm_chunk2<NH, NH, 0, 11>(WP2, s_a, o, zA, zB);
#pragma unroll
        for (int j = 0; j < 11; j++) {
            hA[j] += gelu_f(zA[j] * scA + shA);
            hB[j] += gelu_f(zB[j] * scB + shB);
        }
        gemm_chunk2<NH, NH, 11, 11>(WP2, s_a, o, zA, zB);
#pragma unroll
        for (int j = 0; j < 11; j++) {
            hA[11 + j] += gelu_f(zA[j] * scA + shA);
            hB[11 + j] += gelu_f(zB[j] * scB + shB);
        }
        gemm_chunk2<NH, NH, 22, 11>(WP2, s_a, o, zA, zB);
#pragma unroll
        for (int j = 0; j < 11; j++) {
            hA[22 + j] += gelu_f(zA[j] * scA + shA);
            hB[22 + j] += gelu_f(zB[j] * scB + shB);
        }
    }

    // joint mean -> xt (two columns)
    float msA = 0.f, msB = 0.f;
#pragma unroll
    for (int j = 0; j < NJ; j++) { msA += hA[j]; msB += hB[j]; }
    g_xt[(size_t)bt * NH + o]  = msA * (1.0f / 33.0f);
    g_xt[(size_t)bt * NH + ob] = msB * (1.0f / 33.0f);
}

// ---------------------------------------------------------------------------
// Kernel 2: attention logits.  grid = (NB, 8), block = 128. Each block: 32 t
// (high tW1 L1 reuse per block).
// ---------------------------------------------------------------------------
__global__ void __launch_bounds__(128) score_kernel(
    const float* __restrict__ tW1, const float* __restrict__ tb1,
    const float* __restrict__ tW2, const float* __restrict__ tb2) {
    __shared__ __align__(16) float s_row[NH];
    __shared__ float s_red[4];

    const int tid  = threadIdx.x;
    const int b    = blockIdx.x;
    const int t0   = blockIdx.y * 32;
    const int lane = tid & 31;
    const int wid  = tid >> 5;
    const float* xtb = g_xt + (size_t)b * NT * NH;

    float tb1v = tb1[tid];
    float tw2v = tW2[tid];
    float tb2v = tb2[0];

    for (int ti = 0; ti < 32; ++ti) {
        int t = t0 + ti;
        __syncthreads();                       // protect s_row/s_red reuse
        s_row[tid] = xtb[(size_t)t * NH + tid];
        __syncthreads();
        float acc = tb1v;
#pragma unroll 4
        for (int k = 0; k < NH; k += 4) {
            float4 r = *reinterpret_cast<const float4*>(s_row + k);
            const float* wp = tW1 + k * NH + tid;
            acc += r.x * wp[0];
            acc += r.y * wp[NH];
            acc += r.z * wp[2 * NH];
            acc += r.w * wp[3 * NH];
        }
        float v = gelu_f(acc) * tw2v;
#pragma unroll
        for (int off = 16; off; off >>= 1)
            v += __shfl_xor_sync(0xffffffffu, v, off);
        if (lane == 0) s_red[wid] = v;
        __syncthreads();
        if (tid == 0)
            g_score[b * NT + t] = s_red[0] + s_red[1] + s_red[2] + s_red[3] + tb2v;
    }
}

// ---------------------------------------------------------------------------
// Kernel 3: softmax over T + weighted sum.  grid = NB, block = 512.
// Threads 0..127 own 2 scores each for the softmax; all 512 threads split the
// weighted-sum t-loop 4 ways (col = tid&127, quarter = tid>>7).
// ---------------------------------------------------------------------------
__global__ void __launch_bounds__(512) finalize_kernel(float* __restrict__ out) {
    __shared__ float s_p[NT];
    __shared__ float s_red[16];
    __shared__ float s_part[512];

    const int tid  = threadIdx.x;
    const int b    = blockIdx.x;
    const int lane = tid & 31;
    const int wid  = tid >> 5;

    float sA = -INFINITY, sB = -INFINITY;
    if (tid < 128) {
        sA = g_score[b * NT + tid];
        sB = g_score[b * NT + 128 + tid];
    }

    float mv = fmaxf(sA, sB);
#pragma unroll
    for (int off = 16; off; off >>= 1)
        mv = fmaxf(mv, __shfl_xor_sync(0xffffffffu, mv, off));
    if (lane == 0) s_red[wid] = mv;
    __syncthreads();
    mv = s_red[0];
#pragma unroll
    for (int w = 1; w < 16; w++) mv = fmaxf(mv, s_red[w]);
    __syncthreads();

    float e0 = (tid < 128) ? expf(sA - mv) : 0.f;
    float e1 = (tid < 128) ? expf(sB - mv) : 0.f;
    float sv = e0 + e1;
#pragma unroll
    for (int off = 16; off; off >>= 1)
        sv += __shfl_xor_sync(0xffffffffu, sv, off);
    if (lane == 0) s_red[wid] = sv;
    __syncthreads();
    sv = 0.f;
#pragma unroll
    for (int w = 0; w < 16; w++) sv += s_red[w];
    float inv = 1.0f / sv;

    if (tid < 128) {
        s_p[tid]       = e0 * inv;
        s_p[tid + 128] = e1 * inv;
    }
    __syncthreads();

    // weighted sum: quarter q handles t in [q*64, q*64+64)
    const int col = tid & 127;
    const int q   = tid >> 7;
    const float* xtb = g_xt + (size_t)b * NT * NH + col;
    float a0 = 0.f, a1 = 0.f, a2 = 0.f, a3 = 0.f,
          a4 = 0.f, a5 = 0.f, a6 = 0.f, a7 = 0.f;
    int tb = q * 64;
#pragma unroll 2
    for (int t = tb; t < tb + 64; t += 8) {
        a0 += s_p[t]     * xtb[(size_t)(t)     * NH];
        a1 += s_p[t + 1] * xtb[(size_t)(t + 1) * NH];
        a2 += s_p[t + 2] * xtb[(size_t)(t + 2) * NH];
        a3 += s_p[t + 3] * xtb[(size_t)(t + 3) * NH];
        a4 += s_p[t + 4] * xtb[(size_t)(t + 4) * NH];
        a5 += s_p[t + 5] * xtb[(size_t)(t + 5) * NH];
        a6 += s_p[t + 6] * xtb[(size_t)(t + 6) * NH];
        a7 += s_p[t + 7] * xtb[(size_t)(t + 7) * NH];
    }
    s_part[tid] = ((a0 + a1) + (a2 + a3)) + ((a4 + a5) + (a6 + a7));
    __syncthreads();
    if (tid < 128)
        out[b * NH + tid] =
            (s_part[tid] + s_part[tid + 128]) +
            (s_part[tid + 256] + s_part[tid + 384]);
}

// ---------------------------------------------------------------------------
extern "C" void kernel_launch(void* const* d_in, const int* in_sizes, int n_in,
                              void* d_out, int out_size) {
    const float* x   = (const float*)d_in[0];
    const float* adj = (const float*)d_in[1];
    const float* W0  = (const float*)d_in[2];
    const float* b0  = (const float*)d_in[3];
    const float* S0  = (const float*)d_in[4];
    const float* sb0 = (const float*)d_in[5];
    const float* g0  = (const float*)d_in[6];
    const float* be0 = (const float*)d_in[7];
    const float* m0  = (const float*)d_in[8];
    const float* v0  = (const float*)d_in[9];
    const float* W1  = (const float*)d_in[10];
    const float* b1  = (const float*)d_in[11];
    const float* g1  = (const float*)d_in[12];
    const float* be1 = (const float*)d_in[13];
    const float* m1  = (const float*)d_in[14];
    const float* v1  = (const float*)d_in[15];
    const float* W2  = (const float*)d_in[16];
    const float* b2  = (const float*)d_in[17];
    const float* g2  = (const float*)d_in[18];
    const float* be2 = (const float*)d_in[19];
    const float* m2  = (const float*)d_in[20];
    const float* v2  = (const float*)d_in[21];
    const float* tW1 = (const float*)d_in[22];
    const float* tb1 = (const float*)d_in[23];
    const float* tW2 = (const float*)d_in[24];
    const float* tb2 = (const float*)d_in[25];

    pack_weights_kernel<<<dim3(QR1, 4), NH>>>(W0, S0, W1, W2);
    gcn_kernel<<<BT, 64>>>(x, adj, b0, sb0, g0, be0, m0, v0,
                           b1, g1, be1, m1, v1,
                           b2, g2, be2, m2, v2);
    score_kernel<<<dim3(NB, 8), 128>>>(tW1, tb1, tW2, tb2);
    finalize_kernel<<<NB, 512>>>((float*)d_out);
}

// round 13
// speedup vs baseline: 1.1086x; 1.1086x over previous
// R13: resubmission of R12 (broker died before execution).
// R10 gcn+score (best measured, 1567us total) + R11 finalize (measured 11us).
#include <cuda_runtime.h>
#include <math.h>

#define DEVINL __device__ __forceinline__
typedef unsigned long long ull;

constexpr int NJ  = 33;
constexpr int NF  = 52;
constexpr int NH  = 128;
constexpr int NB  = 64;     // batch
constexpr int NT  = 256;    // time
constexpr int BT  = NB * NT;
constexpr int NNZ = 69;

// Packed-weight scratch: pair-rows of 256 floats ({W[2p][o],W[2p+1][o]} per o)
constexpr int PR0 = NF / 2;   // 26 pair-rows for K=52
constexpr int PR1 = NH / 2;   // 64 pair-rows for K=128
constexpr int OFF_W0 = 0;
constexpr int OFF_S0 = OFF_W0 + PR0 * 2 * NH;     // 6656
constexpr int OFF_W1 = OFF_S0 + PR0 * 2 * NH;     // 13312
constexpr int OFF_W2 = OFF_W1 + PR1 * 2 * NH;     // 29696
__device__ __align__(16) float g_WP[OFF_W2 + PR1 * 2 * NH];   // 46080 floats

// ---------------------------------------------------------------------------
// Hardcoded sparsity of the normalized adjacency (BODY_EDGES + self loops).
// ---------------------------------------------------------------------------
__constant__ int c_ptr[NJ + 1] = {
    0, 5, 6, 9, 10, 11, 14, 15, 18, 21, 22, 23, 30, 37, 40, 43, 45, 47,
    48, 49, 50, 51, 52, 53, 57, 61, 62, 63, 64, 65, 66, 67, 68, 69};
__constant__ int c_col[NNZ] = {
    0, 2, 5, 11, 12,
    1,
    0, 2, 7,
    3,
    4,
    0, 5, 8,
    6,
    2, 7, 11,
    5, 8, 12,
    9,
    10,
    0, 7, 11, 12, 13, 23, 24,
    0, 8, 11, 12, 14, 23, 24,
    11, 13, 15,
    12, 14, 16,
    13, 15,
    14, 16,
    17, 18, 19, 20, 21, 22,
    11, 12, 23, 24,
    11, 12, 23, 24,
    25, 26, 27, 28, 29, 30, 31, 32};
__constant__ int c_row[NNZ] = {
    0, 0, 0, 0, 0,
    1,
    2, 2, 2,
    3,
    4,
    5, 5, 5,
    6,
    7, 7, 7,
    8, 8, 8,
    9,
    10,
    11, 11, 11, 11, 11, 11, 11,
    12, 12, 12, 12, 12, 12, 12,
    13, 13, 13,
    14, 14, 14,
    15, 15,
    16, 16,
    17, 18, 19, 20, 21, 22,
    23, 23, 23, 23,
    24, 24, 24, 24,
    25, 26, 27, 28, 29, 30, 31, 32};

// Scratch (static __device__: allocation-guard safe)
__device__ float g_xt[(size_t)BT * NH];   // per-frame joint-mean features
__device__ float g_score[BT];             // attention logits

// ---------------------------------------------------------------------------
// helpers
// ---------------------------------------------------------------------------
DEVINL float gelu_f(float x) {
    return 0.5f * x * (1.0f + erff(x * 0.70710678118654752440f));
}

DEVINL void unpack2(ull v, float& lo, float& hi) {
    asm("mov.b64 {%0, %1}, %2;" : "=f"(lo), "=f"(hi) : "l"(v));
}
DEVINL void fma2(ull& d, ull a, ull b) {
    asm("fma.rn.f32x2 %0, %1, %2, %0;" : "+l"(d) : "l"(a), "l"(b));
}

// ---------------------------------------------------------------------------
// Weight pre-pack kernel: WP[p][o] = {W[2p][o], W[2p+1][o]}  (float2 per o).
// grid (64, 4), block 128.
// ---------------------------------------------------------------------------
__global__ void pack_weights_kernel(const float* __restrict__ W0,
                                    const float* __restrict__ S0,
                                    const float* __restrict__ W1,
                                    const float* __restrict__ W2) {
    int p = blockIdx.x;
    int m = blockIdx.y;
    int o = threadIdx.x;
    const float* src;
    float* dst;
    int npr;
    if (m == 0)      { src = W0; dst = g_WP + OFF_W0; npr = PR0; }
    else if (m == 1) { src = S0; dst = g_WP + OFF_S0; npr = PR0; }
    else if (m == 2) { src = W1; dst = g_WP + OFF_W1; npr = PR1; }
    else             { src = W2; dst = g_WP + OFF_W2; npr = PR1; }
    if (p >= npr) return;
    float lo = src[(2 * p)     * NH + o];
    float hi = src[(2 * p + 1) * NH + o];
    dst[p * 2 * NH + 2 * o]     = lo;
    dst[p * 2 * NH + 2 * o + 1] = hi;
}

// Two-column GEMM chunk on pair-packed weights (LDG.64 per k-pair, no pack ALU).
template <int K, int LD, int J0, int JN>
DEVINL void gemm_chunk2(const float* __restrict__ WP, const float* s_in, int o,
                        float* zA, float* zB) {
    ull zA2[JN], zB2[JN];
#pragma unroll
    for (int j = 0; j < JN; j++) { zA2[j] = 0ull; zB2[j] = 0ull; }
#pragma unroll 2
    for (int k0 = 0; k0 < K; k0 += 4) {
        const ull* wq = reinterpret_cast<const ull*>(WP + k0 * NH);
        ull wa01 = wq[o];            // {W[k0][o],   W[k0+1][o]}
        ull wa23 = wq[o + 128];      // {W[k0+2][o], W[k0+3][o]}
        ull wb01 = wq[o + 64];       // col o+64
        ull wb23 = wq[o + 192];
#pragma unroll
        for (int j = 0; j < JN; j++) {
            ulonglong2 a2 =
                *reinterpret_cast<const ulonglong2*>(s_in + (J0 + j) * LD + k0);
            fma2(zA2[j], a2.x, wa01);
            fma2(zA2[j], a2.y, wa23);
            fma2(zB2[j], a2.x, wb01);
            fma2(zB2[j], a2.y, wb23);
        }
    }
#pragma unroll
    for (int j = 0; j < JN; j++) {
        float lo, hi;
        unpack2(zA2[j], lo, hi);
        zA[j] = lo + hi;
        unpack2(zB2[j], lo, hi);
        zB[j] = lo + hi;
    }
}

// a = adj_norm @ h for one column, written to s_a[:, col].
DEVINL void adjmix_store(const float h[NJ], const float* s_v, float* s_a, int col) {
    float* p = s_a + col;
#define V(e) s_v[e]
    p[0 * NH]  = V(0)*h[0] + V(1)*h[2] + V(2)*h[5] + V(3)*h[11] + V(4)*h[12];
    p[1 * NH]  = V(5)*h[1];
    p[2 * NH]  = V(6)*h[0] + V(7)*h[2] + V(8)*h[7];
    p[3 * NH]  = V(9)*h[3];
    p[4 * NH]  = V(10)*h[4];
    p[5 * NH]  = V(11)*h[0] + V(12)*h[5] + V(13)*h[8];
    p[6 * NH]  = V(14)*h[6];
    p[7 * NH]  = V(15)*h[2] + V(16)*h[7] + V(17)*h[11];
    p[8 * NH]  = V(18)*h[5] + V(19)*h[8] + V(20)*h[12];
    p[9 * NH]  = V(21)*h[9];
    p[10 * NH] = V(22)*h[10];
    p[11 * NH] = V(23)*h[0] + V(24)*h[7] + V(25)*h[11] + V(26)*h[12] +
                 V(27)*h[13] + V(28)*h[23] + V(29)*h[24];
    p[12 * NH] = V(30)*h[0] + V(31)*h[8] + V(32)*h[11] + V(33)*h[12] +
                 V(34)*h[14] + V(35)*h[23] + V(36)*h[24];
    p[13 * NH] = V(37)*h[11] + V(38)*h[13] + V(39)*h[15];
    p[14 * NH] = V(40)*h[12] + V(41)*h[14] + V(42)*h[16];
    p[15 * NH] = V(43)*h[13] + V(44)*h[15];
    p[16 * NH] = V(45)*h[14] + V(46)*h[16];
    p[17 * NH] = V(47)*h[17];
    p[18 * NH] = V(48)*h[18];
    p[19 * NH] = V(49)*h[19];
    p[20 * NH] = V(50)*h[20];
    p[21 * NH] = V(51)*h[21];
    p[22 * NH] = V(52)*h[22];
    p[23 * NH] = V(53)*h[11] + V(54)*h[12] + V(55)*h[23] + V(56)*h[24];
    p[24 * NH] = V(57)*h[11] + V(58)*h[12] + V(59)*h[23] + V(60)*h[24];
    p[25 * NH] = V(61)*h[25];
    p[26 * NH] = V(62)*h[26];
    p[27 * NH] = V(63)*h[27];
    p[28 * NH] = V(64)*h[28];
    p[29 * NH] = V(65)*h[29];
    p[30 * NH] = V(66)*h[30];
    p[31 * NH] = V(67)*h[31];
    p[32 * NH] = V(68)*h[32];
#undef V
}

// ---------------------------------------------------------------------------
// Kernel 1: fused 3-layer GCN per frame.
// grid = BT, block = 64: thread handles output columns o and o+64.
// ---------------------------------------------------------------------------
__global__ void __launch_bounds__(64, 7) gcn_kernel(
    const float* __restrict__ x,   const float* __restrict__ adj,
    const float* __restrict__ b0,
    const float* __restrict__ sb0,
    const float* __restrict__ g0,  const float* __restrict__ be0,
    const float* __restrict__ m0,  const float* __restrict__ v0,
    const float* __restrict__ b1,
    const float* __restrict__ g1,  const float* __restrict__ be1,
    const float* __restrict__ m1,  const float* __restrict__ v1,
    const float* __restrict__ b2,
    const float* __restrict__ g2,  const float* __restrict__ be2,
    const float* __restrict__ m2,  const float* __restrict__ v2) {
    __shared__ __align__(16) float s_a[NJ * NH];   // 4224 floats
    __shared__ float s_v[NNZ + 3];

    // layer-0 staging overlaid inside s_a (dead after layer 0):
    float* s_x  = s_a;          // 1716 floats  [0, 1716)
    float* s_ax = s_a + 1728;   // 1716 floats  [1728, 3444)  (16B aligned)

    const int o  = threadIdx.x;        // 0..63
    const int ob = o + 64;
    const int bt = blockIdx.x;

    const float* WP0 = g_WP + OFF_W0;
    const float* SP0 = g_WP + OFF_S0;
    const float* WP1 = g_WP + OFF_W1;
    const float* WP2 = g_WP + OFF_W2;

    for (int e = o; e < NNZ; e += 64)
        s_v[e] = adj[c_row[e] * NJ + c_col[e]];

    // load x frame (1716 floats = 429 float4)
    const float4* xin = reinterpret_cast<const float4*>(x + (size_t)bt * (NJ * NF));
    float4* sx4 = reinterpret_cast<float4*>(s_x);
    for (int i = o; i < (NJ * NF) / 4; i += 64) sx4[i] = xin[i];
    __syncthreads();

    // layer-0 adjacency mix on the 52-dim input (sparse)
    for (int idx = o; idx < NJ * NF; idx += 64) {
        int n = idx / NF;
        int k = idx - n * NF;
        float acc = 0.f;
        int e1 = c_ptr[n + 1];
        for (int e = c_ptr[n]; e < e1; ++e)
            acc += s_v[e] * s_x[c_col[e] * NF + k];
        s_ax[idx] = acc;
    }
    __syncthreads();

    float hA[NJ], hB[NJ];
    float zA[11], zB[11];

    // ---- layer 0:  h = gelu(bn(ax @ W0)) + (x @ S0 + sb0) ----
    {
        float scA = g0[o]  * rsqrtf(v0[o]  + 1e-5f);
        float shA = (b0[o]  - m0[o])  * scA + be0[o];
        float scB = g0[ob] * rsqrtf(v0[ob] + 1e-5f);
        float shB = (b0[ob] - m0[ob]) * scB + be0[ob];

        gemm_chunk2<NF, NF, 0, 11>(WP0, s_ax, o, zA, zB);
#pragma unroll
        for (int j = 0; j < 11; j++) {
            hA[j] = gelu_f(zA[j] * scA + shA);
            hB[j] = gelu_f(zB[j] * scB + shB);
        }
        gemm_chunk2<NF, NF, 11, 11>(WP0, s_ax, o, zA, zB);
#pragma unroll
        for (int j = 0; j < 11; j++) {
            hA[11 + j] = gelu_f(zA[j] * scA + shA);
            hB[11 + j] = gelu_f(zB[j] * scB + shB);
        }
        gemm_chunk2<NF, NF, 22, 11>(WP0, s_ax, o, zA, zB);
#pragma unroll
        for (int j = 0; j < 11; j++) {
            hA[22 + j] = gelu_f(zA[j] * scA + shA);
            hB[22 + j] = gelu_f(zB[j] * scB + shB);
        }

        float sbA = sb0[o];
        float sbB = sb0[ob];
        gemm_chunk2<NF, NF, 0, 11>(SP0, s_x, o, zA, zB);
#pragma unroll
        for (int j = 0; j < 11; j++) { hA[j] += zA[j] + sbA; hB[j] += zB[j] + sbB; }
        gemm_chunk2<NF, NF, 11, 11>(SP0, s_x, o, zA, zB);
#pragma unroll
        for (int j = 0; j < 11; j++) { hA[11 + j] += zA[j] + sbA; hB[11 + j] += zB[j] + sbB; }
        gemm_chunk2<NF, NF, 22, 11>(SP0, s_x, o, zA, zB);
#pragma unroll
        for (int j = 0; j < 11; j++) { hA[22 + j] += zA[j] + sbA; hB[22 + j] += zB[j] + sbB; }
    }
    __syncthreads();   // layer-0 reads of s_x/s_ax done before s_a overwrite

    // ---- layer 1 (identity skip) ----
    adjmix_store(hA, s_v, s_a, o);
    adjmix_store(hB, s_v, s_a, ob);
    __syncthreads();
    {
        float scA = g1[o]  * rsqrtf(v1[o]  + 1e-5f);
        float shA = (b1[o]  - m1[o])  * scA + be1[o];
        float scB = g1[ob] * rsqrtf(v1[ob] + 1e-5f);
        float shB = (b1[ob] - m1[ob]) * scB + be1[ob];

        gemm_chunk2<NH, NH, 0, 11>(WP1, s_a, o, zA, zB);
#pragma unroll
        for (int j = 0; j < 11; j++) {
            hA[j] += gelu_f(zA[j] * scA + shA);
            hB[j] += gelu_f(zB[j] * scB + shB);
        }
        gemm_chunk2<NH, NH, 11, 11>(WP1, s_a, o, zA, zB);
#pragma unroll
        for (int j = 0; j < 11; j++) {
            hA[11 + j] += gelu_f(zA[j] * scA + shA);
            hB[11 + j] += gelu_f(zB[j] * scB + shB);
        }
        gemm_chunk2<NH, NH, 22, 11>(WP1, s_a, o, zA, zB);
#pragma unroll
        for (int j = 0; j < 11; j++) {
            hA[22 + j] += gelu_f(zA[j] * scA + shA);
            hB[22 + j] += gelu_f(zB[j] * scB + shB);
        }
    }
    __syncthreads();   // all reads of s_a done before overwrite

    // ---- layer 2 ----
    adjmix_store(hA, s_v, s_a, o);
    adjmix_store(hB, s_v, s_a, ob);
    __syncthreads();
    {
        float scA = g2[o]  * rsqrtf(v2[o]  + 1e-5f);
        float shA = (b2[o]  - m2[o])  * scA + be2[o];
        float scB = g2[ob] * rsqrtf(v2[ob] + 1e-5f);
        float shB = (b2[ob] - m2[ob]) * scB + be2[ob];

        gemm_chunk2<NH, NH, 0, 11>(WP2, s_a, o, zA, zB);
#pragma unroll
        for (int j = 0; j < 11; j++) {
            hA[j] += gelu_f(zA[j] * scA + shA);
            hB[j] += gelu_f(zB[j] * scB + shB);
        }
        gemm_chunk2<NH, NH, 11, 11>(WP2, s_a, o, zA, zB);
#pragma unroll
        for (int j = 0; j < 11; j++) {
            hA[11 + j] += gelu_f(zA[j] * scA + shA);
            hB[11 + j] += gelu_f(zB[j] * scB + shB);
        }
        gemm_chunk2<NH, NH, 22, 11>(WP2, s_a, o, zA, zB);
#pragma unroll
        for (int j = 0; j < 11; j++) {
            hA[22 + j] += gelu_f(zA[j] * scA + shA);
            hB[22 + j] += gelu_f(zB[j] * scB + shB);
        }
    }

    // joint mean -> xt (two columns)
    float msA = 0.f, msB = 0.f;
#pragma unroll
    for (int j = 0; j < NJ; j++) { msA += hA[j]; msB += hB[j]; }
    g_xt[(size_t)bt * NH + o]  = msA * (1.0f / 33.0f);
    g_xt[(size_t)bt * NH + ob] = msB * (1.0f / 33.0f);
}

// ---------------------------------------------------------------------------
// Kernel 2: attention logits.  grid = (NB, 32), block = 128. Each block: 8 t.
// ---------------------------------------------------------------------------
__global__ void __launch_bounds__(128) score_kernel(
    const float* __restrict__ tW1, const float* __restrict__ tb1,
    const float* __restrict__ tW2, const float* __restrict__ tb2) {
    __shared__ __align__(16) float s_row[NH];
    __shared__ float s_red[4];

    const int tid  = threadIdx.x;
    const int b    = blockIdx.x;
    const int t0   = blockIdx.y * 8;
    const int lane = tid & 31;
    const int wid  = tid >> 5;
    const float* xtb = g_xt + (size_t)b * NT * NH;

    float tb1v = tb1[tid];
    float tw2v = tW2[tid];
    float tb2v = tb2[0];

    for (int ti = 0; ti < 8; ++ti) {
        int t = t0 + ti;
        __syncthreads();                       // protect s_row/s_red reuse
        s_row[tid] = xtb[(size_t)t * NH + tid];
        __syncthreads();
        float acc = tb1v;
#pragma unroll 4
        for (int k = 0; k < NH; k += 4) {
            float4 r = *reinterpret_cast<const float4*>(s_row + k);
            const float* wp = tW1 + k * NH + tid;
            acc += r.x * wp[0];
            acc += r.y * wp[NH];
            acc += r.z * wp[2 * NH];
            acc += r.w * wp[3 * NH];
        }
        float v = gelu_f(acc) * tw2v;
#pragma unroll
        for (int off = 16; off; off >>= 1)
            v += __shfl_xor_sync(0xffffffffu, v, off);
        if (lane == 0) s_red[wid] = v;
        __syncthreads();
        if (tid == 0)
            g_score[b * NT + t] = s_red[0] + s_red[1] + s_red[2] + s_red[3] + tb2v;
    }
}

// ---------------------------------------------------------------------------
// Kernel 3: softmax over T + weighted sum.  grid = NB, block = 512.
// Threads 0..127 own 2 scores each for the softmax; all 512 threads split the
// weighted-sum t-loop 4 ways (col = tid&127, quarter = tid>>7).
// ---------------------------------------------------------------------------
__global__ void __launch_bounds__(512) finalize_kernel(float* __restrict__ out) {
    __shared__ float s_p[NT];
    __shared__ float s_red[16];
    __shared__ float s_part[512];

    const int tid  = threadIdx.x;
    const int b    = blockIdx.x;
    const int lane = tid & 31;
    const int wid  = tid >> 5;

    float sA = -INFINITY, sB = -INFINITY;
    if (tid < 128) {
        sA = g_score[b * NT + tid];
        sB = g_score[b * NT + 128 + tid];
    }

    float mv = fmaxf(sA, sB);
#pragma unroll
    for (int off = 16; off; off >>= 1)
        mv = fmaxf(mv, __shfl_xor_sync(0xffffffffu, mv, off));
    if (lane == 0) s_red[wid] = mv;
    __syncthreads();
    mv = s_red[0];
#pragma unroll
    for (int w = 1; w < 16; w++) mv = fmaxf(mv, s_red[w]);
    __syncthreads();

    float e0 = (tid < 128) ? expf(sA - mv) : 0.f;
    float e1 = (tid < 128) ? expf(sB - mv) : 0.f;
    float sv = e0 + e1;
#pragma unroll
    for (int off = 16; off; off >>= 1)
        sv += __shfl_xor_sync(0xffffffffu, sv, off);
    if (lane == 0) s_red[wid] = sv;
    __syncthreads();
    sv = 0.f;
#pragma unroll
    for (int w = 0; w < 16; w++) sv += s_red[w];
    float inv = 1.0f / sv;

    if (tid < 128) {
        s_p[tid]       = e0 * inv;
        s_p[tid + 128] = e1 * inv;
    }
    __syncthreads();

    // weighted sum: quarter q handles t in [q*64, q*64+64)
    const int col = tid & 127;
    const int q   = tid >> 7;
    const float* xtb = g_xt + (size_t)b * NT * NH + col;
    float a0 = 0.f, a1 = 0.f, a2 = 0.f, a3 = 0.f,
          a4 = 0.f, a5 = 0.f, a6 = 0.f, a7 = 0.f;
    int tb = q * 64;
#pragma unroll 2
    for (int t = tb; t < tb + 64; t += 8) {
        a0 += s_p[t]     * xtb[(size_t)(t)     * NH];
        a1 += s_p[t + 1] * xtb[(size_t)(t + 1) * NH];
        a2 += s_p[t + 2] * xtb[(size_t)(t + 2) * NH];
        a3 += s_p[t + 3] * xtb[(size_t)(t + 3) * NH];
        a4 += s_p[t + 4] * xtb[(size_t)(t + 4) * NH];
        a5 += s_p[t + 5] * xtb[(size_t)(t + 5) * NH];
        a6 += s_p[t + 6] * xtb[(size_t)(t + 6) * NH];
        a7 += s_p[t + 7] * xtb[(size_t)(t + 7) * NH];
    }
    s_part[tid] = ((a0 + a1) + (a2 + a3)) + ((a4 + a5) + (a6 + a7));
    __syncthreads();
    if (tid < 128)
        out[b * NH + tid] =
            (s_part[tid] + s_part[tid + 128]) +
            (s_part[tid + 256] + s_part[tid + 384]);
}

// ---------------------------------------------------------------------------
extern "C" void kernel_launch(void* const* d_in, const int* in_sizes, int n_in,
                              void* d_out, int out_size) {
    const float* x   = (const float*)d_in[0];
    const float* adj = (const float*)d_in[1];
    const float* W0  = (const float*)d_in[2];
    const float* b0  = (const float*)d_in[3];
    const float* S0  = (const float*)d_in[4];
    const float* sb0 = (const float*)d_in[5];
    const float* g0  = (const float*)d_in[6];
    const float* be0 = (const float*)d_in[7];
    const float* m0  = (const float*)d_in[8];
    const float* v0  = (const float*)d_in[9];
    const float* W1  = (const float*)d_in[10];
    const float* b1  = (const float*)d_in[11];
    const float* g1  = (const float*)d_in[12];
    const float* be1 = (const float*)d_in[13];
    const float* m1  = (const float*)d_in[14];
    const float* v1  = (const float*)d_in[15];
    const float* W2  = (const float*)d_in[16];
    const float* b2  = (const float*)d_in[17];
    const float* g2  = (const float*)d_in[18];
    const float* be2 = (const float*)d_in[19];
    const float* m2  = (const float*)d_in[20];
    const float* v2  = (const float*)d_in[21];
    const float* tW1 = (const float*)d_in[22];
    const float* tb1 = (const float*)d_in[23];
    const float* tW2 = (const float*)d_in[24];
    const float* tb2 = (const float*)d_in[25];

    pack_weights_kernel<<<dim3(PR1, 4), NH>>>(W0, S0, W1, W2);
    gcn_kernel<<<BT, 64>>>(x, adj, b0, sb0, g0, be0, m0, v0,
                           b1, g1, be1, m1, v1,
                           b2, g2, be2, m2, v2);
    score_kernel<<<dim3(NB, 32), 128>>>(tW1, tb1, tW2, tb2);
    finalize_kernel<<<NB, 512>>>((float*)d_out);
}

// round 17
// speedup vs baseline: 1.1123x; 1.0033x over previous
// R13: resubmission of R12 (broker died before execution).
// R10 gcn+score (best measured, 1567us total) + R11 finalize (measured 11us).
#include <cuda_runtime.h>
#include <math.h>

#define DEVINL __device__ __forceinline__
typedef unsigned long long ull;

constexpr int NJ  = 33;
constexpr int NF  = 52;
constexpr int NH  = 128;
constexpr int NB  = 64;     // batch
constexpr int NT  = 256;    // time
constexpr int BT  = NB * NT;
constexpr int NNZ = 69;

// Packed-weight scratch: pair-rows of 256 floats ({W[2p][o],W[2p+1][o]} per o)
constexpr int PR0 = NF / 2;   // 26 pair-rows for K=52
constexpr int PR1 = NH / 2;   // 64 pair-rows for K=128
constexpr int OFF_W0 = 0;
constexpr int OFF_S0 = OFF_W0 + PR0 * 2 * NH;     // 6656
constexpr int OFF_W1 = OFF_S0 + PR0 * 2 * NH;     // 13312
constexpr int OFF_W2 = OFF_W1 + PR1 * 2 * NH;     // 29696
__device__ __align__(16) float g_WP[OFF_W2 + PR1 * 2 * NH];   // 46080 floats

// ---------------------------------------------------------------------------
// Hardcoded sparsity of the normalized adjacency (BODY_EDGES + self loops).
// ---------------------------------------------------------------------------
__constant__ int c_ptr[NJ + 1] = {
    0, 5, 6, 9, 10, 11, 14, 15, 18, 21, 22, 23, 30, 37, 40, 43, 45, 47,
    48, 49, 50, 51, 52, 53, 57, 61, 62, 63, 64, 65, 66, 67, 68, 69};
__constant__ int c_col[NNZ] = {
    0, 2, 5, 11, 12,
    1,
    0, 2, 7,
    3,
    4,
    0, 5, 8,
    6,
    2, 7, 11,
    5, 8, 12,
    9,
    10,
    0, 7, 11, 12, 13, 23, 24,
    0, 8, 11, 12, 14, 23, 24,
    11, 13, 15,
    12, 14, 16,
    13, 15,
    14, 16,
    17, 18, 19, 20, 21, 22,
    11, 12, 23, 24,
    11, 12, 23, 24,
    25, 26, 27, 28, 29, 30, 31, 32};
__constant__ int c_row[NNZ] = {
    0, 0, 0, 0, 0,
    1,
    2, 2, 2,
    3,
    4,
    5, 5, 5,
    6,
    7, 7, 7,
    8, 8, 8,
    9,
    10,
    11, 11, 11, 11, 11, 11, 11,
    12, 12, 12, 12, 12, 12, 12,
    13, 13, 13,
    14, 14, 14,
    15, 15,
    16, 16,
    17, 18, 19, 20, 21, 22,
    23, 23, 23, 23,
    24, 24, 24, 24,
    25, 26, 27, 28, 29, 30, 31, 32};

// Scratch (static __device__: allocation-guard safe)
__device__ float g_xt[(size_t)BT * NH];   // per-frame joint-mean features
__device__ float g_score[BT];             // attention logits

// ---------------------------------------------------------------------------
// helpers
// ---------------------------------------------------------------------------
DEVINL float gelu_f(float x) {
    return 0.5f * x * (1.0f + erff(x * 0.70710678118654752440f));
}

DEVINL void unpack2(ull v, float& lo, float& hi) {
    asm("mov.b64 {%0, %1}, %2;" : "=f"(lo), "=f"(hi) : "l"(v));
}
DEVINL void fma2(ull& d, ull a, ull b) {
    asm("fma.rn.f32x2 %0, %1, %2, %0;" : "+l"(d) : "l"(a), "l"(b));
}

// ---------------------------------------------------------------------------
// Weight pre-pack kernel: WP[p][o] = {W[2p][o], W[2p+1][o]}  (float2 per o).
// grid (64, 4), block 128.
// ---------------------------------------------------------------------------
__global__ void pack_weights_kernel(const float* __restrict__ W0,
                                    const float* __restrict__ S0,
                                    const float* __restrict__ W1,
                                    const float* __restrict__ W2) {
    int p = blockIdx.x;
    int m = blockIdx.y;
    int o = threadIdx.x;
    const float* src;
    float* dst;
    int npr;
    if (m == 0)      { src = W0; dst = g_WP + OFF_W0; npr = PR0; }
    else if (m == 1) { src = S0; dst = g_WP + OFF_S0; npr = PR0; }
    else if (m == 2) { src = W1; dst = g_WP + OFF_W1; npr = PR1; }
    else             { src = W2; dst = g_WP + OFF_W2; npr = PR1; }
    if (p >= npr) return;
    float lo = src[(2 * p)     * NH + o];
    float hi = src[(2 * p + 1) * NH + o];
    dst[p * 2 * NH + 2 * o]     = lo;
    dst[p * 2 * NH + 2 * o + 1] = hi;
}

// Two-column GEMM chunk on pair-packed weights (LDG.64 per k-pair, no pack ALU).
template <int K, int LD, int J0, int JN>
DEVINL void gemm_chunk2(const float* __restrict__ WP, const float* s_in, int o,
                        float* zA, float* zB) {
    ull zA2[JN], zB2[JN];
#pragma unroll
    for (int j = 0; j < JN; j++) { zA2[j] = 0ull; zB2[j] = 0ull; }
#pragma unroll 2
    for (int k0 = 0; k0 < K; k0 += 4) {
        const ull* wq = reinterpret_cast<const ull*>(WP + k0 * NH);
        ull wa01 = wq[o];            // {W[k0][o],   W[k0+1][o]}
        ull wa23 = wq[o + 128];      // {W[k0+2][o], W[k0+3][o]}
        ull wb01 = wq[o + 64];       // col o+64
        ull wb23 = wq[o + 192];
#pragma unroll
        for (int j = 0; j < JN; j++) {
            ulonglong2 a2 =
                *reinterpret_cast<const ulonglong2*>(s_in + (J0 + j) * LD + k0);
            fma2(zA2[j], a2.x, wa01);
            fma2(zA2[j], a2.y, wa23);
            fma2(zB2[j], a2.x, wb01);
            fma2(zB2[j], a2.y, wb23);
        }
    }
#pragma unroll
    for (int j = 0; j < JN; j++) {
        float lo, hi;
        unpack2(zA2[j], lo, hi);
        zA[j] = lo + hi;
        unpack2(zB2[j], lo, hi);
        zB[j] = lo + hi;
    }
}

// a = adj_norm @ h for one column, written to s_a[:, col].
DEVINL void adjmix_store(const float h[NJ], const float* s_v, float* s_a, int col) {
    float* p = s_a + col;
#define V(e) s_v[e]
    p[0 * NH]  = V(0)*h[0] + V(1)*h[2] + V(2)*h[5] + V(3)*h[11] + V(4)*h[12];
    p[1 * NH]  = V(5)*h[1];
    p[2 * NH]  = V(6)*h[0] + V(7)*h[2] + V(8)*h[7];
    p[3 * NH]  = V(9)*h[3];
    p[4 * NH]  = V(10)*h[4];
    p[5 * NH]  = V(11)*h[0] + V(12)*h[5] + V(13)*h[8];
    p[6 * NH]  = V(14)*h[6];
    p[7 * NH]  = V(15)*h[2] + V(16)*h[7] + V(17)*h[11];
    p[8 * NH]  = V(18)*h[5] + V(19)*h[8] + V(20)*h[12];
    p[9 * NH]  = V(21)*h[9];
    p[10 * NH] = V(22)*h[10];
    p[11 * NH] = V(23)*h[0] + V(24)*h[7] + V(25)*h[11] + V(26)*h[12] +
                 V(27)*h[13] + V(28)*h[23] + V(29)*h[24];
    p[12 * NH] = V(30)*h[0] + V(31)*h[8] + V(32)*h[11] + V(33)*h[12] +
                 V(34)*h[14] + V(35)*h[23] + V(36)*h[24];
    p[13 * NH] = V(37)*h[11] + V(38)*h[13] + V(39)*h[15];
    p[14 * NH] = V(40)*h[12] + V(41)*h[14] + V(42)*h[16];
    p[15 * NH] = V(43)*h[13] + V(44)*h[15];
    p[16 * NH] = V(45)*h[14] + V(46)*h[16];
    p[17 * NH] = V(47)*h[17];
    p[18 * NH] = V(48)*h[18];
    p[19 * NH] = V(49)*h[19];
    p[20 * NH] = V(50)*h[20];
    p[21 * NH] = V(51)*h[21];
    p[22 * NH] = V(52)*h[22];
    p[23 * NH] = V(53)*h[11] + V(54)*h[12] + V(55)*h[23] + V(56)*h[24];
    p[24 * NH] = V(57)*h[11] + V(58)*h[12] + V(59)*h[23] + V(60)*h[24];
    p[25 * NH] = V(61)*h[25];
    p[26 * NH] = V(62)*h[26];
    p[27 * NH] = V(63)*h[27];
    p[28 * NH] = V(64)*h[28];
    p[29 * NH] = V(65)*h[29];
    p[30 * NH] = V(66)*h[30];
    p[31 * NH] = V(67)*h[31];
    p[32 * NH] = V(68)*h[32];
#undef V
}

// ---------------------------------------------------------------------------
// Kernel 1: fused 3-layer GCN per frame.
// grid = BT, block = 64: thread handles output columns o and o+64.
// ---------------------------------------------------------------------------
__global__ void __launch_bounds__(64, 7) gcn_kernel(
    const float* __restrict__ x,   const float* __restrict__ adj,
    const float* __restrict__ b0,
    const float* __restrict__ sb0,
    const float* __restrict__ g0,  const float* __restrict__ be0,
    const float* __restrict__ m0,  const float* __restrict__ v0,
    const float* __restrict__ b1,
    const float* __restrict__ g1,  const float* __restrict__ be1,
    const float* __restrict__ m1,  const float* __restrict__ v1,
    const float* __restrict__ b2,
    const float* __restrict__ g2,  const float* __restrict__ be2,
    const float* __restrict__ m2,  const float* __restrict__ v2) {
    __shared__ __align__(16) float s_a[NJ * NH];   // 4224 floats
    __shared__ float s_v[NNZ + 3];

    // layer-0 staging overlaid inside s_a (dead after layer 0):
    float* s_x  = s_a;          // 1716 floats  [0, 1716)
    float* s_ax = s_a + 1728;   // 1716 floats  [1728, 3444)  (16B aligned)

    const int o  = threadIdx.x;        // 0..63
    const int ob = o + 64;
    const int bt = blockIdx.x;

    const float* WP0 = g_WP + OFF_W0;
    const float* SP0 = g_WP + OFF_S0;
    const float* WP1 = g_WP + OFF_W1;
    const float* WP2 = g_WP + OFF_W2;

    for (int e = o; e < NNZ; e += 64)
        s_v[e] = adj[c_row[e] * NJ + c_col[e]];

    // load x frame (1716 floats = 429 float4)
    const float4* xin = reinterpret_cast<const float4*>(x + (size_t)bt * (NJ * NF));
    float4* sx4 = reinterpret_cast<float4*>(s_x);
    for (int i = o; i < (NJ * NF) / 4; i += 64) sx4[i] = xin[i];
    __syncthreads();

    // layer-0 adjacency mix on the 52-dim input (sparse)
    for (int idx = o; idx < NJ * NF; idx += 64) {
        int n = idx / NF;
        int k = idx - n * NF;
        float acc = 0.f;
        int e1 = c_ptr[n + 1];
        for (int e = c_ptr[n]; e < e1; ++e)
            acc += s_v[e] * s_x[c_col[e] * NF + k];
        s_ax[idx] = acc;
    }
    __syncthreads();

    float hA[NJ], hB[NJ];
    float zA[11], zB[11];

    // ---- layer 0:  h = gelu(bn(ax @ W0)) + (x @ S0 + sb0) ----
    {
        float scA = g0[o]  * rsqrtf(v0[o]  + 1e-5f);
        float shA = (b0[o]  - m0[o])  * scA + be0[o];
        float scB = g0[ob] * rsqrtf(v0[ob] + 1e-5f);
        float shB = (b0[ob] - m0[ob]) * scB + be0[ob];

        gemm_chunk2<NF, NF, 0, 11>(WP0, s_ax, o, zA, zB);
#pragma unroll
        for (int j = 0; j < 11; j++) {
            hA[j] = gelu_f(zA[j] * scA + shA);
            hB[j] = gelu_f(zB[j] * scB + shB);
        }
        gemm_chunk2<NF, NF, 11, 11>(WP0, s_ax, o, zA, zB);
#pragma unroll
        for (int j = 0; j < 11; j++) {
            hA[11 + j] = gelu_f(zA[j] * scA + shA);
            hB[11 + j] = gelu_f(zB[j] * scB + shB);
        }
        gemm_chunk2<NF, NF, 22, 11>(WP0, s_ax, o, zA, zB);
#pragma unroll
        for (int j = 0; j < 11; j++) {
            hA[22 + j] = gelu_f(zA[j] * scA + shA);
            hB[22 + j] = gelu_f(zB[j] * scB + shB);
        }

        float sbA = sb0[o];
        float sbB = sb0[ob];
        gemm_chunk2<NF, NF, 0, 11>(SP0, s_x, o, zA, zB);
#pragma unroll
        for (int j = 0; j < 11; j++) { hA[j] += zA[j] + sbA; hB[j] += zB[j] + sbB; }
        gemm_chunk2<NF, NF, 11, 11>(SP0, s_x, o, zA, zB);
#pragma unroll
        for (int j = 0; j < 11; j++) { hA[11 + j] += zA[j] + sbA; hB[11 + j] += zB[j] + sbB; }
        gemm_chunk2<NF, NF, 22, 11>(SP0, s_x, o, zA, zB);
#pragma unroll
        for (int j = 0; j < 11; j++) { hA[22 + j] += zA[j] + sbA; hB[22 + j] += zB[j] + sbB; }
    }
    __syncthreads();   // layer-0 reads of s_x/s_ax done before s_a overwrite

    // ---- layer 1 (identity skip) ----
    adjmix_store(hA, s_v, s_a, o);
    adjmix_store(hB, s_v, s_a, ob);
    __syncthreads();
    {
        float scA = g1[o]  * rsqrtf(v1[o]  + 1e-5f);
        float shA = (b1[o]  - m1[o])  * scA + be1[o];
        float scB = g1[ob] * rsqrtf(v1[ob] + 1e-5f);
        float shB = (b1[ob] - m1[ob]) * scB + be1[ob];

        gemm_chunk2<NH, NH, 0, 11>(WP1, s_a, o, zA, zB);
#pragma unroll
        for (int j = 0; j < 11; j++) {
            hA[j] += gelu_f(zA[j] * scA + shA);
            hB[j] += gelu_f(zB[j] * scB + shB);
        }
        gemm_chunk2<NH, NH, 11, 11>(WP1, s_a, o, zA, zB);
#pragma unroll
        for (int j = 0; j < 11; j++) {
            hA[11 + j] += gelu_f(zA[j] * scA + shA);
            hB[11 + j] += gelu_f(zB[j] * scB + shB);
        }
        gemm_chunk2<NH, NH, 22, 11>(WP1, s_a, o, zA, zB);
#pragma unroll
        for (int j = 0; j < 11; j++) {
            hA[22 + j] += gelu_f(zA[j] * scA + shA);
            hB[22 + j] += gelu_f(zB[j] * scB + shB);
        }
    }
    __syncthreads();   // all reads of s_a done before overwrite

    // ---- layer 2 ----
    adjmix_store(hA, s_v, s_a, o);
    adjmix_store(hB, s_v, s_a, ob);
    __syncthreads();
    {
        float scA = g2[o]  * rsqrtf(v2[o]  + 1e-5f);
        float shA = (b2[o]  - m2[o])  * scA + be2[o];
        float scB = g2[ob] * rsqrtf(v2[ob] + 1e-5f);
        float shB = (b2[ob] - m2[ob]) * scB + be2[ob];

        gemm_chunk2<NH, NH, 0, 11>(WP2, s_a, o, zA, zB);
#pragma unroll
        for (int j = 0; j < 11; j++) {
            hA[j] += gelu_f(zA[j] * scA + shA);
            hB[j] += gelu_f(zB[j] * scB + shB);
        }
        gemm_chunk2<NH, NH, 11, 11>(WP2, s_a, o, zA, zB);
#pragma unroll
        for (int j = 0; j < 11; j++) {
            hA[11 + j] += gelu_f(zA[j] * scA + shA);
            hB[11 + j] += gelu_f(zB[j] * scB + shB);
        }
        gemm_chunk2<NH, NH, 22, 11>(WP2, s_a, o, zA, zB);
#pragma unroll
        for (int j = 0; j < 11; j++) {
            hA[22 + j] += gelu_f(zA[j] * scA + shA);
            hB[22 + j] += gelu_f(zB[j] * scB + shB);
        }
    }

    // joint mean -> xt (two columns)
    float msA = 0.f, msB = 0.f;
#pragma unroll
    for (int j = 0; j < NJ; j++) { msA += hA[j]; msB += hB[j]; }
    g_xt[(size_t)bt * NH + o]  = msA * (1.0f / 33.0f);
    g_xt[(size_t)bt * NH + ob] = msB * (1.0f / 33.0f);
}

// ---------------------------------------------------------------------------
// Kernel 2: attention logits.  grid = (NB, 32), block = 128. Each block: 8 t.
// ---------------------------------------------------------------------------
__global__ void __launch_bounds__(128) score_kernel(
    const float* __restrict__ tW1, const float* __restrict__ tb1,
    const float* __restrict__ tW2, const float* __restrict__ tb2) {
    __shared__ __align__(16) float s_row[NH];
    __shared__ float s_red[4];

    const int tid  = threadIdx.x;
    const int b    = blockIdx.x;
    const int t0   = blockIdx.y * 8;
    const int lane = tid & 31;
    const int wid  = tid >> 5;
    const float* xtb = g_xt + (size_t)b * NT * NH;

    float tb1v = tb1[tid];
    float tw2v = tW2[tid];
    float tb2v = tb2[0];

    for (int ti = 0; ti < 8; ++ti) {
        int t = t0 + ti;
        __syncthreads();                       // protect s_row/s_red reuse
        s_row[tid] = xtb[(size_t)t * NH + tid];
        __syncthreads();
        float acc = tb1v;
#pragma unroll 4
        for (int k = 0; k < NH; k += 4) {
            float4 r = *reinterpret_cast<const float4*>(s_row + k);
            const float* wp = tW1 + k * NH + tid;
            acc += r.x * wp[0];
            acc += r.y * wp[NH];
            acc += r.z * wp[2 * NH];
            acc += r.w * wp[3 * NH];
        }
        float v = gelu_f(acc) * tw2v;
#pragma unroll
        for (int off = 16; off; off >>= 1)
            v += __shfl_xor_sync(0xffffffffu, v, off);
        if (lane == 0) s_red[wid] = v;
        __syncthreads();
        if (tid == 0)
            g_score[b * NT + t] = s_red[0] + s_red[1] + s_red[2] + s_red[3] + tb2v;
    }
}

// ---------------------------------------------------------------------------
// Kernel 3: softmax over T + weighted sum.  grid = NB, block = 512.
// Threads 0..127 own 2 scores each for the softmax; all 512 threads split the
// weighted-sum t-loop 4 ways (col = tid&127, quarter = tid>>7).
// ---------------------------------------------------------------------------
__global__ void __launch_bounds__(512) finalize_kernel(float* __restrict__ out) {
    __shared__ float s_p[NT];
    __shared__ float s_red[16];
    __shared__ float s_part[512];

    const int tid  = threadIdx.x;
    const int b    = blockIdx.x;
    const int lane = tid & 31;
    const int wid  = tid >> 5;

    float sA = -INFINITY, sB = -INFINITY;
    if (tid < 128) {
        sA = g_score[b * NT + tid];
        sB = g_score[b * NT + 128 + tid];
    }

    float mv = fmaxf(sA, sB);
#pragma unroll
    for (int off = 16; off; off >>= 1)
        mv = fmaxf(mv, __shfl_xor_sync(0xffffffffu, mv, off));
    if (lane == 0) s_red[wid] = mv;
    __syncthreads();
    mv = s_red[0];
#pragma unroll
    for (int w = 1; w < 16; w++) mv = fmaxf(mv, s_red[w]);
    __syncthreads();

    float e0 = (tid < 128) ? expf(sA - mv) : 0.f;
    float e1 = (tid < 128) ? expf(sB - mv) : 0.f;
    float sv = e0 + e1;
#pragma unroll
    for (int off = 16; off; off >>= 1)
        sv += __shfl_xor_sync(0xffffffffu, sv, off);
    if (lane == 0) s_red[wid] = sv;
    __syncthreads();
    sv = 0.f;
#pragma unroll
    for (int w = 0; w < 16; w++) sv += s_red[w];
    float inv = 1.0f / sv;

    if (tid < 128) {
        s_p[tid]       = e0 * inv;
        s_p[tid + 128] = e1 * inv;
    }
    __syncthreads();

    // weighted sum: quarter q handles t in [q*64, q*64+64)
    const int col = tid & 127;
    const int q   = tid >> 7;
    const float* xtb = g_xt + (size_t)b * NT * NH + col;
    float a0 = 0.f, a1 = 0.f, a2 = 0.f, a3 = 0.f,
          a4 = 0.f, a5 = 0.f, a6 = 0.f, a7 = 0.f;
    int tb = q * 64;
#pragma unroll 2
    for (int t = tb; t < tb + 64; t += 8) {
        a0 += s_p[t]     * xtb[(size_t)(t)     * NH];
        a1 += s_p[t + 1] * xtb[(size_t)(t + 1) * NH];
        a2 += s_p[t + 2] * xtb[(size_t)(t + 2) * NH];
        a3 += s_p[t + 3] * xtb[(size_t)(t + 3) * NH];
        a4 += s_p[t + 4] * xtb[(size_t)(t + 4) * NH];
        a5 += s_p[t + 5] * xtb[(size_t)(t + 5) * NH];
        a6 += s_p[t + 6] * xtb[(size_t)(t + 6) * NH];
        a7 += s_p[t + 7] * xtb[(size_t)(t + 7) * NH];
    }
    s_part[tid] = ((a0 + a1) + (a2 + a3)) + ((a4 + a5) + (a6 + a7));
    __syncthreads();
    if (tid < 128)
        out[b * NH + tid] =
            (s_part[tid] + s_part[tid + 128]) +
            (s_part[tid + 256] + s_part[tid + 384]);
}

// ---------------------------------------------------------------------------
extern "C" void kernel_launch(void* const* d_in, const int* in_sizes, int n_in,
                              void* d_out, int out_size) {
    const float* x   = (const float*)d_in[0];
    const float* adj = (const float*)d_in[1];
    const float* W0  = (const float*)d_in[2];
    const float* b0  = (const float*)d_in[3];
    const float* S0  = (const float*)d_in[4];
    const float* sb0 = (const float*)d_in[5];
    const float* g0  = (const float*)d_in[6];
    const float* be0 = (const float*)d_in[7];
    const float* m0  = (const float*)d_in[8];
    const float* v0  = (const float*)d_in[9];
    const float* W1  = (const float*)d_in[10];
    const float* b1  = (const float*)d_in[11];
    const float* g1  = (const float*)d_in[12];
    const float* be1 = (const float*)d_in[13];
    const float* m1  = (const float*)d_in[14];
    const float* v1  = (const float*)d_in[15];
    const float* W2  = (const float*)d_in[16];
    const float* b2  = (const float*)d_in[17];
    const float* g2  = (const float*)d_in[18];
    const float* be2 = (const float*)d_in[19];
    const float* m2  = (const float*)d_in[20];
    const float* v2  = (const float*)d_in[21];
    const float* tW1 = (const float*)d_in[22];
    const float* tb1 = (const float*)d_in[23];
    const float* tW2 = (const float*)d_in[24];
    const float* tb2 = (const float*)d_in[25];

    pack_weights_kernel<<<dim3(PR1, 4), NH>>>(W0, S0, W1, W2);
    gcn_kernel<<<BT, 64>>>(x, adj, b0, sb0, g0, be0, m0, v0,
                           b1, g1, be1, m1, v1,
                           b2, g2, be2, m2, v2);
    score_kernel<<<dim3(NB, 32), 128>>>(tW1, tb1, tW2, tb2);
    finalize_kernel<<<NB, 512>>>((float*)d_out);
}